// round 10
// baseline (speedup 1.0000x reference)
#include <cuda_runtime.h>
#include <cstdint>

#define N_NODES 100000
#define N_EDGES 1250000
#define D 64
#define MAX_DEG 96   // Poisson(12.5): P(deg > 96) < 1e-40

typedef unsigned long long ull;

// ---- device scratch (no allocation allowed) ----
// g_cnt relies on two invariants:
//   1) __device__ globals are zero-initialized at module load (first call).
//   2) gmlp_kernel re-zeros every counter it reads (subsequent calls).
__device__ int g_cnt[N_NODES];                                  // degree/cursor
__device__ __align__(16) int g_bkt[(size_t)N_NODES * MAX_DEG];  // 38.4 MB

// ---- f32x2 helpers ----
__device__ __forceinline__ ull pk2(float lo, float hi) {
    ull r;
    asm("mov.b64 %0, {%1, %2};" : "=l"(r) : "f"(lo), "f"(hi));
    return r;
}
__device__ __forceinline__ void upk2(float& lo, float& hi, ull v) {
    asm("mov.b64 {%0, %1}, %2;" : "=f"(lo), "=f"(hi) : "l"(v));
}
#define FMA2(acc, a, b) \
    asm("fma.rn.f32x2 %0, %1, %2, %3;" : "=l"(acc) : "l"(a), "l"(b), "l"(acc))

// ---------------------------------------------------------------------------
// Kernel 1: single-pass bucket fill. pos = cnt[dst]++; bkt[dst*96+pos] = src.
// Dtype detection done in-block: warp 0 reads 32 odd 32-bit words in parallel
// and ballots. int64 little-endian => high words of values <100000 are all 0;
// int32 => those words are random node ids (P[all 32 zero] ~ 1e-160).
// 1 edge per thread (max warps hide the ~318cyc atomic-return latency).
// ---------------------------------------------------------------------------
__global__ __launch_bounds__(512) void fillbkt_kernel(const void* __restrict__ ei) {
    __shared__ int s_is64;
    if (threadIdx.x < 32) {
        int w = ((const int*)ei)[threadIdx.x * 2 + 1];
        unsigned nz = __ballot_sync(0xffffffffu, w != 0);
        if (threadIdx.x == 0) s_is64 = (nz == 0u);
    }
    __syncthreads();

    int e = blockIdx.x * blockDim.x + threadIdx.x;
    if (e >= N_EDGES) return;
    int s, d;
    if (s_is64) {
        const long long* p = (const long long*)ei;
        s = (int)__ldg(&p[e]);
        d = (int)__ldg(&p[N_EDGES + e]);
    } else {
        const int* p = (const int*)ei;
        s = __ldg(&p[e]);
        d = __ldg(&p[N_EDGES + e]);
    }
    int pos = atomicAdd(&g_cnt[d], 1);
    if (pos < MAX_DEG) g_bkt[(size_t)d * MAX_DEG + pos] = s;
}

// ---------------------------------------------------------------------------
// Kernel 2: fused gather + MLP.
// Block = 256 threads, tile = 64 nodes.
// Gather: half-warp per node; indices read as int4 broadcast LDG.128 from the
//         node's contiguous bucket (4 idx/load), software-prefetched; each
//         lane loads one float4 chunk of each neighbor row. Lane 0 of each
//         half-warp re-zeros the node's counter for the next call.
// MLP:    register-tiled 4x4 per thread, packed f32x2 FFMA2; W2 staged into
//         the same smem buffer during the ReLU-writeback barrier window.
// ---------------------------------------------------------------------------
#define HS_STRIDE 68  // 64 + 4 pad; multiple of 4 keeps float4 alignment

__global__ __launch_bounds__(256) void gmlp_kernel(
    const float* __restrict__ x,
    const float* __restrict__ W1, const float* __restrict__ b1,
    const float* __restrict__ W2, const float* __restrict__ b2,
    float* __restrict__ out)
{
    __shared__ float Ws[D * D];          // 16 KB, reused for W1 then W2
    __shared__ float hs[64][HS_STRIDE];  // 17.4 KB

    const int tid = threadIdx.x;
    const int node_base = blockIdx.x * 64;
    const float4* __restrict__ x4 = (const float4*)x;

    // Stage W1 (float4); consumed only after the gather barrier.
    #pragma unroll
    for (int i = tid; i < D * D / 4; i += 256) {
        reinterpret_cast<float4*>(Ws)[i] = reinterpret_cast<const float4*>(W1)[i];
    }

    // ---- Phase 1: gather h = x[n] + sum_{src in N(n)} x[src] ----
    {
        const int hw = tid >> 4;   // half-warp id 0..15, 4 nodes each
        const int hl = tid & 15;   // float4 chunk within row
        #pragma unroll 1
        for (int i = 0; i < 4; i++) {
            int nd = hw * 4 + i;
            int g = node_base + nd;
            float4 a = make_float4(0.f, 0.f, 0.f, 0.f);
            if (g < N_NODES) {
                a = x4[(size_t)g * 16 + hl];
                int deg = g_cnt[g];
                if (hl == 0) g_cnt[g] = 0;  // reset for the next call
                if (deg > MAX_DEG) deg = MAX_DEG;
                const int4* b4 = (const int4*)(g_bkt + (size_t)g * MAX_DEG);

                int j = 0;
                if (deg >= 4) {
                    int4 idc = b4[0];
                    // prefetched 4-wide loop
                    for (; j + 8 <= deg; j += 4) {
                        int4 idn = b4[(j >> 2) + 1];
                        float4 v0 = x4[(size_t)idc.x * 16 + hl];
                        float4 v1 = x4[(size_t)idc.y * 16 + hl];
                        float4 v2 = x4[(size_t)idc.z * 16 + hl];
                        float4 v3 = x4[(size_t)idc.w * 16 + hl];
                        a.x += v0.x + v1.x + v2.x + v3.x;
                        a.y += v0.y + v1.y + v2.y + v3.y;
                        a.z += v0.z + v1.z + v2.z + v3.z;
                        a.w += v0.w + v1.w + v2.w + v3.w;
                        idc = idn;
                    }
                    // last full quad
                    {
                        float4 v0 = x4[(size_t)idc.x * 16 + hl];
                        float4 v1 = x4[(size_t)idc.y * 16 + hl];
                        float4 v2 = x4[(size_t)idc.z * 16 + hl];
                        float4 v3 = x4[(size_t)idc.w * 16 + hl];
                        a.x += v0.x + v1.x + v2.x + v3.x;
                        a.y += v0.y + v1.y + v2.y + v3.y;
                        a.z += v0.z + v1.z + v2.z + v3.z;
                        a.w += v0.w + v1.w + v2.w + v3.w;
                        j += 4;
                    }
                }
                for (; j < deg; j++) {
                    int s0 = g_bkt[(size_t)g * MAX_DEG + j];
                    float4 v0 = x4[(size_t)s0 * 16 + hl];
                    a.x += v0.x; a.y += v0.y; a.z += v0.z; a.w += v0.w;
                }
            }
            *reinterpret_cast<float4*>(&hs[nd][hl * 4]) = a;
        }
    }
    __syncthreads();

    // ---- Phase 2: MLP (f32x2 packed) ----
    const int tx = tid & 15;
    const int ty = tid >> 4;
    ull a01[4], a23[4];

    // Layer 1: t = relu(h @ W1 + b1)
    {
        float4 bv = reinterpret_cast<const float4*>(b1)[tx];
        ull b01 = pk2(bv.x, bv.y), b23 = pk2(bv.z, bv.w);
        #pragma unroll
        for (int r = 0; r < 4; r++) { a01[r] = b01; a23[r] = b23; }
    }
    #pragma unroll 4
    for (int k0 = 0; k0 < D; k0 += 4) {
        float hr[4][4];
        #pragma unroll
        for (int r = 0; r < 4; r++) {
            *reinterpret_cast<float4*>(hr[r]) =
                *reinterpret_cast<const float4*>(&hs[ty * 4 + r][k0]);
        }
        #pragma unroll
        for (int kk = 0; kk < 4; kk++) {
            float4 w = *reinterpret_cast<const float4*>(&Ws[(k0 + kk) * D + tx * 4]);
            ull w01 = pk2(w.x, w.y), w23 = pk2(w.z, w.w);
            #pragma unroll
            for (int r = 0; r < 4; r++) {
                ull hh = pk2(hr[r][kk], hr[r][kk]);
                FMA2(a01[r], hh, w01);
                FMA2(a23[r], hh, w23);
            }
        }
    }
    __syncthreads();  // layer-1 reads of Ws and hs complete

    // ReLU write-back into hs + stage W2 into Ws (same barrier window).
    #pragma unroll
    for (int r = 0; r < 4; r++) {
        float t0, t1, t2, t3;
        upk2(t0, t1, a01[r]);
        upk2(t2, t3, a23[r]);
        float4 t = make_float4(fmaxf(t0, 0.f), fmaxf(t1, 0.f),
                               fmaxf(t2, 0.f), fmaxf(t3, 0.f));
        *reinterpret_cast<float4*>(&hs[ty * 4 + r][tx * 4]) = t;
    }
    #pragma unroll
    for (int i = tid; i < D * D / 4; i += 256) {
        reinterpret_cast<float4*>(Ws)[i] = reinterpret_cast<const float4*>(W2)[i];
    }
    __syncthreads();

    // Layer 2: out = t @ W2 + b2
    {
        float4 bv = reinterpret_cast<const float4*>(b2)[tx];
        ull b01 = pk2(bv.x, bv.y), b23 = pk2(bv.z, bv.w);
        #pragma unroll
        for (int r = 0; r < 4; r++) { a01[r] = b01; a23[r] = b23; }
    }
    #pragma unroll 4
    for (int k0 = 0; k0 < D; k0 += 4) {
        float hr[4][4];
        #pragma unroll
        for (int r = 0; r < 4; r++) {
            *reinterpret_cast<float4*>(hr[r]) =
                *reinterpret_cast<const float4*>(&hs[ty * 4 + r][k0]);
        }
        #pragma unroll
        for (int kk = 0; kk < 4; kk++) {
            float4 w = *reinterpret_cast<const float4*>(&Ws[(k0 + kk) * D + tx * 4]);
            ull w01 = pk2(w.x, w.y), w23 = pk2(w.z, w.w);
            #pragma unroll
            for (int r = 0; r < 4; r++) {
                ull hh = pk2(hr[r][kk], hr[r][kk]);
                FMA2(a01[r], hh, w01);
                FMA2(a23[r], hh, w23);
            }
        }
    }

    #pragma unroll
    for (int r = 0; r < 4; r++) {
        int g = node_base + ty * 4 + r;
        if (g < N_NODES) {
            float o0, o1, o2, o3;
            upk2(o0, o1, a01[r]);
            upk2(o2, o3, a23[r]);
            reinterpret_cast<float4*>(out)[(size_t)g * 16 + tx] =
                make_float4(o0, o1, o2, o3);
        }
    }
}

// ---------------------------------------------------------------------------
// Launch. Inputs (metadata order): x, edge_index, W1, b1, W2, b2
// Two kernels total: bucket fill -> fused gather+MLP.
// ---------------------------------------------------------------------------
extern "C" void kernel_launch(void* const* d_in, const int* in_sizes, int n_in,
                              void* d_out, int out_size) {
    const float* x  = (const float*)d_in[0];
    const void*  ei = d_in[1];
    const float* W1 = (const float*)d_in[2];
    const float* b1 = (const float*)d_in[3];
    const float* W2 = (const float*)d_in[4];
    const float* b2 = (const float*)d_in[5];
    float* out = (float*)d_out;

    fillbkt_kernel<<<(N_EDGES + 511) / 512, 512>>>(ei);

    gmlp_kernel<<<(N_NODES + 63) / 64, 256>>>(x, W1, b1, W2, b2, out);
}

// round 11
// speedup vs baseline: 1.5529x; 1.5529x over previous
#include <cuda_runtime.h>
#include <cstdint>

#define N_NODES 100000
#define N_EDGES 1250000
#define D 64
#define MAX_DEG 96   // Poisson(12.5): P(deg > 96) < 1e-40

typedef unsigned long long ull;

// ---- device scratch (no allocation allowed) ----
// g_cnt relies on two invariants:
//   1) __device__ globals are zero-initialized at module load (first call).
//   2) gmlp_kernel re-zeros every counter in its epilogue (subsequent calls).
__device__ int g_cnt[N_NODES];                                  // degree/cursor
__device__ __align__(16) int g_bkt[(size_t)N_NODES * MAX_DEG];  // 38.4 MB

// ---- f32x2 helpers ----
__device__ __forceinline__ ull pk2(float lo, float hi) {
    ull r;
    asm("mov.b64 %0, {%1, %2};" : "=l"(r) : "f"(lo), "f"(hi));
    return r;
}
__device__ __forceinline__ void upk2(float& lo, float& hi, ull v) {
    asm("mov.b64 {%0, %1}, %2;" : "=f"(lo), "=f"(hi) : "l"(v));
}
#define FMA2(acc, a, b) \
    asm("fma.rn.f32x2 %0, %1, %2, %3;" : "=l"(acc) : "l"(a), "l"(b), "l"(acc))

// ---------------------------------------------------------------------------
// Kernel 1: single-pass bucket fill. pos = cnt[dst]++; bkt[dst*96+pos] = src.
// Dtype detection in-block: warp 0 reads 32 odd 32-bit words in parallel and
// ballots. int64 little-endian => high words of values <100000 are all 0;
// int32 => those words are random node ids (P[all 32 zero] ~ 1e-160).
// 1 edge per thread (max warps hide the ~318cyc atomic-return latency).
// ---------------------------------------------------------------------------
__global__ __launch_bounds__(512) void fillbkt_kernel(const void* __restrict__ ei) {
    __shared__ int s_is64;
    if (threadIdx.x < 32) {
        int w = ((const int*)ei)[threadIdx.x * 2 + 1];
        unsigned nz = __ballot_sync(0xffffffffu, w != 0);
        if (threadIdx.x == 0) s_is64 = (nz == 0u);
    }
    __syncthreads();

    int e = blockIdx.x * blockDim.x + threadIdx.x;
    if (e >= N_EDGES) return;
    int s, d;
    if (s_is64) {
        const long long* p = (const long long*)ei;
        s = (int)__ldg(&p[e]);
        d = (int)__ldg(&p[N_EDGES + e]);
    } else {
        const int* p = (const int*)ei;
        s = __ldg(&p[e]);
        d = __ldg(&p[N_EDGES + e]);
    }
    int pos = atomicAdd(&g_cnt[d], 1);
    if (pos < MAX_DEG) g_bkt[(size_t)d * MAX_DEG + pos] = s;
}

// ---------------------------------------------------------------------------
// Kernel 2: fused gather + MLP.
// Block = 256 threads, tile = 64 nodes.
// Gather: half-warp per node; indices read as int4 broadcast LDG.128 from the
//         node's contiguous bucket, software-prefetched; each lane loads one
//         float4 chunk of each neighbor row. LOADS ONLY — no global stores in
//         this phase (a store here blocks load batching via possible aliasing).
// MLP:    register-tiled 4x4 per thread, packed f32x2 FFMA2; W2 staged into
//         the same smem buffer during the ReLU-writeback barrier window.
// Epilogue: tid<64 re-zero the tile's counters for the next call.
// ---------------------------------------------------------------------------
#define HS_STRIDE 68  // 64 + 4 pad; multiple of 4 keeps float4 alignment

__global__ __launch_bounds__(256) void gmlp_kernel(
    const float* __restrict__ x,
    const float* __restrict__ W1, const float* __restrict__ b1,
    const float* __restrict__ W2, const float* __restrict__ b2,
    float* __restrict__ out)
{
    __shared__ float Ws[D * D];          // 16 KB, reused for W1 then W2
    __shared__ float hs[64][HS_STRIDE];  // 17.4 KB

    const int tid = threadIdx.x;
    const int node_base = blockIdx.x * 64;
    const float4* __restrict__ x4 = (const float4*)x;

    // Stage W1 (float4); consumed only after the gather barrier.
    #pragma unroll
    for (int i = tid; i < D * D / 4; i += 256) {
        reinterpret_cast<float4*>(Ws)[i] = reinterpret_cast<const float4*>(W1)[i];
    }

    // ---- Phase 1: gather h = x[n] + sum_{src in N(n)} x[src] ----
    {
        const int hw = tid >> 4;   // half-warp id 0..15, 4 nodes each
        const int hl = tid & 15;   // float4 chunk within row
        #pragma unroll 1
        for (int i = 0; i < 4; i++) {
            int nd = hw * 4 + i;
            int g = node_base + nd;
            float4 a = make_float4(0.f, 0.f, 0.f, 0.f);
            if (g < N_NODES) {
                a = x4[(size_t)g * 16 + hl];
                int deg = g_cnt[g];
                if (deg > MAX_DEG) deg = MAX_DEG;
                const int4* b4 = (const int4*)(g_bkt + (size_t)g * MAX_DEG);

                int j = 0;
                if (deg >= 4) {
                    int4 idc = b4[0];
                    // prefetched 4-wide loop
                    for (; j + 8 <= deg; j += 4) {
                        int4 idn = b4[(j >> 2) + 1];
                        float4 v0 = x4[(size_t)idc.x * 16 + hl];
                        float4 v1 = x4[(size_t)idc.y * 16 + hl];
                        float4 v2 = x4[(size_t)idc.z * 16 + hl];
                        float4 v3 = x4[(size_t)idc.w * 16 + hl];
                        a.x += v0.x + v1.x + v2.x + v3.x;
                        a.y += v0.y + v1.y + v2.y + v3.y;
                        a.z += v0.z + v1.z + v2.z + v3.z;
                        a.w += v0.w + v1.w + v2.w + v3.w;
                        idc = idn;
                    }
                    // last full quad
                    {
                        float4 v0 = x4[(size_t)idc.x * 16 + hl];
                        float4 v1 = x4[(size_t)idc.y * 16 + hl];
                        float4 v2 = x4[(size_t)idc.z * 16 + hl];
                        float4 v3 = x4[(size_t)idc.w * 16 + hl];
                        a.x += v0.x + v1.x + v2.x + v3.x;
                        a.y += v0.y + v1.y + v2.y + v3.y;
                        a.z += v0.z + v1.z + v2.z + v3.z;
                        a.w += v0.w + v1.w + v2.w + v3.w;
                        j += 4;
                    }
                }
                for (; j < deg; j++) {
                    int s0 = g_bkt[(size_t)g * MAX_DEG + j];
                    float4 v0 = x4[(size_t)s0 * 16 + hl];
                    a.x += v0.x; a.y += v0.y; a.z += v0.z; a.w += v0.w;
                }
            }
            *reinterpret_cast<float4*>(&hs[nd][hl * 4]) = a;
        }
    }
    __syncthreads();

    // ---- Phase 2: MLP (f32x2 packed) ----
    const int tx = tid & 15;
    const int ty = tid >> 4;
    ull a01[4], a23[4];

    // Layer 1: t = relu(h @ W1 + b1)
    {
        float4 bv = reinterpret_cast<const float4*>(b1)[tx];
        ull b01 = pk2(bv.x, bv.y), b23 = pk2(bv.z, bv.w);
        #pragma unroll
        for (int r = 0; r < 4; r++) { a01[r] = b01; a23[r] = b23; }
    }
    #pragma unroll 4
    for (int k0 = 0; k0 < D; k0 += 4) {
        float hr[4][4];
        #pragma unroll
        for (int r = 0; r < 4; r++) {
            *reinterpret_cast<float4*>(hr[r]) =
                *reinterpret_cast<const float4*>(&hs[ty * 4 + r][k0]);
        }
        #pragma unroll
        for (int kk = 0; kk < 4; kk++) {
            float4 w = *reinterpret_cast<const float4*>(&Ws[(k0 + kk) * D + tx * 4]);
            ull w01 = pk2(w.x, w.y), w23 = pk2(w.z, w.w);
            #pragma unroll
            for (int r = 0; r < 4; r++) {
                ull hh = pk2(hr[r][kk], hr[r][kk]);
                FMA2(a01[r], hh, w01);
                FMA2(a23[r], hh, w23);
            }
        }
    }
    __syncthreads();  // layer-1 reads of Ws and hs complete

    // ReLU write-back into hs + stage W2 into Ws (same barrier window).
    #pragma unroll
    for (int r = 0; r < 4; r++) {
        float t0, t1, t2, t3;
        upk2(t0, t1, a01[r]);
        upk2(t2, t3, a23[r]);
        float4 t = make_float4(fmaxf(t0, 0.f), fmaxf(t1, 0.f),
                               fmaxf(t2, 0.f), fmaxf(t3, 0.f));
        *reinterpret_cast<float4*>(&hs[ty * 4 + r][tx * 4]) = t;
    }
    #pragma unroll
    for (int i = tid; i < D * D / 4; i += 256) {
        reinterpret_cast<float4*>(Ws)[i] = reinterpret_cast<const float4*>(W2)[i];
    }
    __syncthreads();

    // Layer 2: out = t @ W2 + b2
    {
        float4 bv = reinterpret_cast<const float4*>(b2)[tx];
        ull b01 = pk2(bv.x, bv.y), b23 = pk2(bv.z, bv.w);
        #pragma unroll
        for (int r = 0; r < 4; r++) { a01[r] = b01; a23[r] = b23; }
    }
    #pragma unroll 4
    for (int k0 = 0; k0 < D; k0 += 4) {
        float hr[4][4];
        #pragma unroll
        for (int r = 0; r < 4; r++) {
            *reinterpret_cast<float4*>(hr[r]) =
                *reinterpret_cast<const float4*>(&hs[ty * 4 + r][k0]);
        }
        #pragma unroll
        for (int kk = 0; kk < 4; kk++) {
            float4 w = *reinterpret_cast<const float4*>(&Ws[(k0 + kk) * D + tx * 4]);
            ull w01 = pk2(w.x, w.y), w23 = pk2(w.z, w.w);
            #pragma unroll
            for (int r = 0; r < 4; r++) {
                ull hh = pk2(hr[r][kk], hr[r][kk]);
                FMA2(a01[r], hh, w01);
                FMA2(a23[r], hh, w23);
            }
        }
    }

    #pragma unroll
    for (int r = 0; r < 4; r++) {
        int g = node_base + ty * 4 + r;
        if (g < N_NODES) {
            float o0, o1, o2, o3;
            upk2(o0, o1, a01[r]);
            upk2(o2, o3, a23[r]);
            reinterpret_cast<float4*>(out)[(size_t)g * 16 + tx] =
                make_float4(o0, o1, o2, o3);
        }
    }

    // ---- Epilogue: re-zero this tile's counters for the next call. ----
    // After all gather reads (ordered by the barriers above). One coalesced
    // 256B store per tile, outside every hot loop.
    if (tid < 64) {
        int g = node_base + tid;
        if (g < N_NODES) g_cnt[g] = 0;
    }
}

// ---------------------------------------------------------------------------
// Launch. Inputs (metadata order): x, edge_index, W1, b1, W2, b2
// Two kernels total: bucket fill -> fused gather+MLP.
// ---------------------------------------------------------------------------
extern "C" void kernel_launch(void* const* d_in, const int* in_sizes, int n_in,
                              void* d_out, int out_size) {
    const float* x  = (const float*)d_in[0];
    const void*  ei = d_in[1];
    const float* W1 = (const float*)d_in[2];
    const float* b1 = (const float*)d_in[3];
    const float* W2 = (const float*)d_in[4];
    const float* b2 = (const float*)d_in[5];
    float* out = (float*)d_out;

    fillbkt_kernel<<<(N_EDGES + 511) / 512, 512>>>(ei);

    gmlp_kernel<<<(N_NODES + 63) / 64, 256>>>(x, W1, b1, W2, b2, out);
}